// round 14
// baseline (speedup 1.0000x reference)
#include <cuda_runtime.h>
#include <cuda_fp16.h>
#include <math.h>
#include <stdint.h>

#define NTHR 512
#define TEDGE 64
#define EPAD 65

// ---------------- device scratch (static, no allocation) ----------------
__device__ float g_w3j[11 * 125];        // per-instruction wigner3j, pre-scaled by PW[l3]
__device__ uint4 g_W2H[11 * 32 * 4 * 2 * 32];  // W2 in fp16 B-fragment layout (1.44 MB)
__device__ __half g_Hh[20000 * 64];      // weight-NN hidden activations (fp16)
__device__ float g_agg[2048 * 288];      // message aggregation buffer (zeroed by final_kernel)

// irrep constants
constexpr int DIMS_[3] = {1, 3, 5};
constexpr int SO_[3]   = {0, 1, 4};     // offsets into 9-dim sh
constexpr int KO_[3]   = {0, 1, 4};     // offsets into 9-slot accumulator
constexpr int LO_[3]   = {0, 16, 64};   // LOCAL x offsets for a 16-u half (16+48+80=144 ch)

// fp16 m16n8k16 MMA, D += A*B (fp32 accumulate)
__device__ __forceinline__ void mma_f16(float* d, const uint32_t* a, uint32_t b0, uint32_t b1) {
    asm volatile(
        "mma.sync.aligned.m16n8k16.row.col.f32.f16.f16.f32 "
        "{%0,%1,%2,%3}, {%4,%5,%6,%7}, {%8,%9}, {%0,%1,%2,%3};\n"
        : "+f"(d[0]), "+f"(d[1]), "+f"(d[2]), "+f"(d[3])
        : "r"(a[0]), "r"(a[1]), "r"(a[2]), "r"(a[3]), "r"(b0), "r"(b1));
}

// ======================= wigner-3j setup (reference algorithm) =======================
__device__ __forceinline__ double dfact(int n) {
    double r = 1.0;
    for (int i = 2; i <= n; i++) r *= (double)i;
    return r;
}

__device__ void build_q(int l, double* qr, double* qi) {
    int D = 2 * l + 1;
    for (int i = 0; i < D * D; i++) { qr[i] = 0.0; qi[i] = 0.0; }
    const double s2 = 0.70710678118654752440;
    for (int m = -l; m < 0; m++) {
        qr[(l + m) * D + (l - m)] = s2;
        qi[(l + m) * D + (l + m)] = -s2;
    }
    qr[l * D + l] = 1.0;
    for (int m = 1; m <= l; m++) {
        double sg = (m & 1) ? -1.0 : 1.0;
        qr[(l + m) * D + (l + m)] = sg * s2;
        qi[(l + m) * D + (l - m)] = sg * s2;
    }
    double fr, fi;
    switch (l & 3) {
        case 0: fr = 1;  fi = 0;  break;
        case 1: fr = 0;  fi = -1; break;
        case 2: fr = -1; fi = 0;  break;
        default: fr = 0; fi = 1;  break;
    }
    for (int i = 0; i < D * D; i++) {
        double r = qr[i], im = qi[i];
        qr[i] = r * fr - im * fi;
        qi[i] = r * fi + im * fr;
    }
}

__global__ void w3j_setup_kernel() {
    const int L1[11] = {0, 0, 0, 1, 1, 1, 1, 2, 2, 2, 2};
    const int L2[11] = {0, 1, 2, 0, 1, 1, 2, 0, 1, 2, 2};
    const int L3[11] = {0, 1, 2, 1, 0, 2, 1, 2, 1, 0, 2};
    int t = blockIdx.x;
    int j1 = L1[t], j2 = L2[t], j3 = L3[t];
    int d1 = 2 * j1 + 1, d2 = 2 * j2 + 1, d3 = 2 * j3 + 1;
    __shared__ double Cs[125];
    __shared__ double Q1r[25], Q1i[25], Q2r[25], Q2i[25], Q3r[25], Q3i[25];
    __shared__ double outv[125];
    __shared__ double scale_s;
    int tid = threadIdx.x;
    if (tid < 125) Cs[tid] = 0.0;
    if (tid == 0) {
        build_q(j1, Q1r, Q1i);
        build_q(j2, Q2r, Q2i);
        build_q(j3, Q3r, Q3i);
    }
    __syncthreads();
    if (tid < d1 * d2) {
        int m1 = tid / d2 - j1;
        int m2 = tid % d2 - j2;
        int m3 = m1 + m2;
        if (m3 >= -j3 && m3 <= j3) {
            int vmin = -j1 + j2 + m3;
            if (-j1 + m1 > vmin) vmin = -j1 + m1;
            if (vmin < 0) vmin = 0;
            int vmax = j2 + j3 + m1;
            if (j3 - j1 + j2 < vmax) vmax = j3 - j1 + j2;
            if (j3 + m3 < vmax) vmax = j3 + m3;
            double c = sqrt((double)(2 * j3 + 1) * dfact(j3 + j1 - j2) * dfact(j3 - j1 + j2) *
                            dfact(j1 + j2 - j3) * dfact(j3 + m3) * dfact(j3 - m3) /
                            (dfact(j1 + j2 + j3 + 1) * dfact(j1 - m1) * dfact(j1 + m1) *
                             dfact(j2 - m2) * dfact(j2 + m2)));
            double s = 0.0;
            for (int v = vmin; v <= vmax; v++) {
                double term = dfact(j2 + j3 + m1 - v) * dfact(j1 - m1 + v) /
                              (dfact(v) * dfact(j3 - j1 + j2 - v) * dfact(j3 + m3 - v) *
                               dfact(v + j1 - j2 - m3));
                if ((v + j2 + m2) & 1) term = -term;
                s += term;
            }
            Cs[((m1 + j1) * d2 + (m2 + j2)) * d3 + (m3 + j3)] = c * s;
        }
    }
    __syncthreads();
    int nel = d1 * d2 * d3;
    if (tid < nel) {
        int jj = tid / (d2 * d3);
        int ll = (tid / d3) % d2;
        int mm = tid % d3;
        double ar = 0.0;
        for (int i = 0; i < d1; i++)
            for (int k = 0; k < d2; k++)
                for (int n = 0; n < d3; n++) {
                    double cv = Cs[(i * d2 + k) * d3 + n];
                    if (cv == 0.0) continue;
                    double p1r = Q1r[i * d1 + jj], p1i = Q1i[i * d1 + jj];
                    double p2r = Q2r[k * d2 + ll], p2i = Q2i[k * d2 + ll];
                    double p3r = Q3r[n * d3 + mm], p3i = -Q3i[n * d3 + mm];
                    double t1r = p1r * p2r - p1i * p2i;
                    double t1i = p1r * p2i + p1i * p2r;
                    double t2r = t1r * p3r - t1i * p3i;
                    ar += t2r * cv;
                }
        outv[tid] = ar;
    }
    __syncthreads();
    if (tid == 0) {
        const double PWv[3] = {0.10206207261596575, 0.15309310892394862, 0.19764235376052370};
        double s = 0.0;
        for (int i = 0; i < nel; i++) s += outv[i] * outv[i];
        scale_s = PWv[j3] / sqrt(s);
    }
    __syncthreads();
    if (tid < nel) g_w3j[t * 125 + tid] = (float)(outv[tid] * scale_s);
}

// ======================= W2 relayout into fp16 B-fragment order =======================
__global__ void w2h_kernel(const float* __restrict__ W2) {
    int idx = blockIdx.x * 256 + threadIdx.x;
    if (idx >= 64 * 11264) return;
    int c = idx / 11264;
    int col = idx - c * 11264;
    int ins = col >> 10;
    int rem = col & 1023;
    int u = rem >> 5;
    int w = rem & 31;
    int wtile = w >> 3, n = w & 7;
    int q = c >> 4, cl = c & 15;
    int hsel = cl >> 3;
    int c8 = cl & 7;
    int tig = c8 >> 1, pp = c8 & 1;
    int lane = (n << 2) | tig;
    int q2 = q >> 1, qq = q & 1;
    int u4 = (((ins * 32 + u) * 4 + wtile) * 2 + q2) * 32 + lane;
    int hidx = u4 * 8 + (qq * 2 + hsel) * 2 + pp;
    ((__half*)g_W2H)[hidx] = __float2half(W2[idx] * 0.125f);
}

// ======================= weight-NN hidden layer (fp16 output) =======================
__global__ void h_kernel(const float* __restrict__ radial, const float* __restrict__ W1,
                         float cst, int E) {
    __shared__ float rs[4][64];
    int le = threadIdx.x >> 6, c = threadIdx.x & 63;
    int e = blockIdx.x * 4 + le;
    rs[le][c] = (e < E) ? radial[e * 64 + c] : 0.f;
    __syncthreads();
    float a = 0.f;
#pragma unroll
    for (int r = 0; r < 64; r++) a += rs[le][r] * W1[r * 64 + c];
    a *= 0.125f;  // 1/sqrt(64)
    float hv = cst * a / (1.f + expf(-a));
    if (e < E) g_Hh[e * 64 + c] = __float2half(hv);
}

// ======================= fused message kernel (persistent, u-split units) ==========
// Work unit = (64-edge tile) x (16-u half). 626 units over grid=min(296, nunits).
// Block = 512 threads = 16 warps. Warp wid: wtile = wid&3, rtile = wid>>2.

// z for 16 local u's: thread owns edge e = tid&63, u = (tid>>6) + s*8, s<2.
template <int D1, int D2, int D3, int SO2, int O1, int W3OFF>
__device__ __forceinline__ void compute_z(const float* __restrict__ xs,
                                          float* __restrict__ zb,
                                          const float* __restrict__ shT,
                                          const float* __restrict__ w3j_s, int tid) {
    int e = tid & 63;
    int u0 = tid >> 6;  // 0..7
    float shv[D2];
#pragma unroll
    for (int j = 0; j < D2; j++) shv[j] = shT[(SO2 + j) * EPAD + e];
    float sv[D1 * D3];
#pragma unroll
    for (int i = 0; i < D1; i++)
#pragma unroll
        for (int k = 0; k < D3; k++) {
            float a = 0.f;
#pragma unroll
            for (int j = 0; j < D2; j++)
                a += w3j_s[W3OFF + (i * D2 + j) * D3 + k] * shv[j];
            sv[i * D3 + k] = a;
        }
#pragma unroll
    for (int s = 0; s < 2; s++) {
        int u = u0 + s * 8;  // local u 0..15
        float xv[D1];
#pragma unroll
        for (int i = 0; i < D1; i++) xv[i] = xs[(O1 + u * D1 + i) * EPAD + e];
#pragma unroll
        for (int k = 0; k < D3; k++) {
            float z = 0.f;
#pragma unroll
            for (int i = 0; i < D1; i++) z += xv[i] * sv[i * D3 + k];
            zb[(u * D3 + k) * EPAD + e] = z;
        }
    }
}

// Consume one local u: 4 MMAs (2 independent chains) + z-weighted accumulation.
template <int D3, int KO>
__device__ __forceinline__ void consume_u(const float* __restrict__ zb,
                                          const uint32_t (&af)[4][4], float (&acc)[4][9],
                                          int u, int er0, int er1,
                                          const uint4& Ba, const uint4& Bb) {
    float c0[4] = {0.f, 0.f, 0.f, 0.f};
    float c1[4] = {0.f, 0.f, 0.f, 0.f};
    mma_f16(c0, af[0], Ba.x, Ba.y);
    mma_f16(c1, af[1], Ba.z, Ba.w);
    mma_f16(c0, af[2], Bb.x, Bb.y);
    mma_f16(c1, af[3], Bb.z, Bb.w);
    float wv0 = c0[0] + c1[0];
    float wv1 = c0[1] + c1[1];
    float wv2 = c0[2] + c1[2];
    float wv3 = c0[3] + c1[3];
#pragma unroll
    for (int k = 0; k < D3; k++) {
        float z0 = zb[(u * D3 + k) * EPAD + er0];
        float z1 = zb[(u * D3 + k) * EPAD + er1];
        acc[0][KO + k] += wv0 * z0;
        acc[1][KO + k] += wv1 * z0;
        acc[2][KO + k] += wv2 * z1;
        acc[3][KO + k] += wv3 * z1;
    }
}

// MMA phase for one ins over 16 local u's; uoff = ubase*256 (uint4 units).
template <int D3, int KO, int PB>
__device__ __forceinline__ void mma_phase(const float* __restrict__ zb,
                                          const uint32_t (&af)[4][4], float (&acc)[4][9],
                                          int lane, int wtile, int er0, int er1, int uoff) {
    const uint4* __restrict__ Bp = g_W2H + PB + uoff + wtile * 64 + lane;
    uint4 s0a = __ldg(Bp +   0), s0b = __ldg(Bp +  32);   // u=0
    uint4 s1a = __ldg(Bp + 256), s1b = __ldg(Bp + 288);   // u=1
    uint4 s2a = __ldg(Bp + 512), s2b = __ldg(Bp + 544);   // u=2
    uint4 s3a = __ldg(Bp + 768), s3b = __ldg(Bp + 800);   // u=3
#pragma unroll 1
    for (int ub = 0; ub < 16; ub += 4) {
        bool more = ub < 12;
        consume_u<D3, KO>(zb, af, acc, ub + 0, er0, er1, s0a, s0b);
        if (more) { const uint4* B = Bp + (ub + 4) * 256; s0a = __ldg(B); s0b = __ldg(B + 32); }
        consume_u<D3, KO>(zb, af, acc, ub + 1, er0, er1, s1a, s1b);
        if (more) { const uint4* B = Bp + (ub + 5) * 256; s1a = __ldg(B); s1b = __ldg(B + 32); }
        consume_u<D3, KO>(zb, af, acc, ub + 2, er0, er1, s2a, s2b);
        if (more) { const uint4* B = Bp + (ub + 6) * 256; s2a = __ldg(B); s2b = __ldg(B + 32); }
        consume_u<D3, KO>(zb, af, acc, ub + 3, er0, er1, s3a, s3b);
        if (more) { const uint4* B = Bp + (ub + 7) * 256; s3a = __ldg(B); s3b = __ldg(B + 32); }
    }
}

// per-ins template args: A=i1, B=i2, C=i3
#define CZ(IDX, A, B, Cc, BUF)                                                          \
    compute_z<DIMS_[A], DIMS_[B], DIMS_[Cc], SO_[B], LO_[A], IDX * 125>(                \
        xs, BUF, shT, w3j_s, tid)
#define MP(IDX, A, B, Cc, BUF)                                                          \
    mma_phase<DIMS_[Cc], KO_[Cc], IDX * 8192>(BUF, af, acc, lane, wtile, er0, er1, uoff)

__global__ void __launch_bounds__(NTHR, 1)
msg_kernel(const float* __restrict__ nf, const int* __restrict__ ei,
           const float* __restrict__ shg, int E, int nunits) {
    extern __shared__ float smem[];
    float* xs    = smem;                          // 144*65 = 9360 (local u-half channels)
    __half* hsm  = (__half*)(xs + 144 * EPAD);    // 64*64 halves (2048 floats)
    float* zb0   = xs + 144 * EPAD + TEDGE * 32;  // 16*5*65 = 5200
    float* zb1   = zb0 + 16 * 5 * EPAD;           // 16*5*65
    float* shT   = zb1 + 16 * 5 * EPAD;           // 9*65 = 585
    float* w3j_s = shT + 9 * EPAD;                // 1375
    int* srcdst  = (int*)(w3j_s + 1375);          // 128 ints
    int tid = threadIdx.x;

    // loop-invariant: w3j table (visibility covered by loop-top barrier)
    for (int idx = tid; idx < 11 * 125; idx += NTHR) w3j_s[idx] = g_w3j[idx];

    int lane = tid & 31;
    int wid = tid >> 5;
    int rtile = wid >> 2, wtile = wid & 3;
    int g = lane >> 2, tig = lane & 3;
    int er0 = rtile * 16 + g, er1 = er0 + 8;
    int wc0 = wtile * 8 + 2 * tig, wc1 = wc0 + 1;
    const uint32_t* hs2 = (const uint32_t*)hsm;

    for (int unit = blockIdx.x; unit < nunits; unit += gridDim.x) {
        int tile = unit >> 1;
        int ubase = (unit & 1) << 4;   // 0 or 16
        int uoff = ubase << 8;         // ubase*256 uint4 units
        int e0 = tile * TEDGE;
        __syncthreads();  // previous unit's smem readers done (and w3j_s visible, 1st iter)

        if (tid < 128) {
            int e = e0 + (tid & 63);
            int which = tid >> 6;
            srcdst[tid] = (e < E) ? ei[which * E + e] : 0;
        }
        __syncthreads();
        // x: only the 144 channels for u in [ubase, ubase+16)
        for (int idx = tid; idx < TEDGE * 144; idx += NTHR) {
            int e = idx / 144;
            int c = idx - e * 144;
            int gc;
            if (c < 16) {
                gc = ubase + c;
            } else if (c < 64) {
                int r = c - 16;
                int ul = r / 3, i = r - ul * 3;
                gc = 32 + (ubase + ul) * 3 + i;
            } else {
                int r = c - 64;
                int ul = r / 5, i = r - ul * 5;
                gc = 128 + (ubase + ul) * 5 + i;
            }
            xs[c * EPAD + e] = (e0 + e < E) ? nf[srcdst[e] * 288 + gc] : 0.f;
        }
        for (int idx = tid; idx < TEDGE * 64; idx += NTHR) {
            int e = idx >> 6;
            int c = idx & 63;
            hsm[e * 64 + c] = (e0 + e < E) ? g_Hh[(e0 + e) * 64 + c] : __float2half(0.f);
        }
        for (int idx = tid; idx < TEDGE * 9; idx += NTHR) {
            int e = idx & 63;
            int j = idx >> 6;
            shT[j * EPAD + e] = (e0 + e < E) ? shg[(e0 + e) * 9 + j] : 0.f;
        }
        __syncthreads();  // hsm/xs/shT ready

        // A fragments (h, fp16 half2-packed)
        uint32_t af[4][4];
#pragma unroll
        for (int q = 0; q < 4; q++) {
            af[q][0] = hs2[er0 * 32 + q * 8 + tig];
            af[q][1] = hs2[er1 * 32 + q * 8 + tig];
            af[q][2] = hs2[er0 * 32 + q * 8 + 4 + tig];
            af[q][3] = hs2[er1 * 32 + q * 8 + 4 + tig];
        }

        float acc[4][9];
#pragma unroll
        for (int p = 0; p < 4; p++)
#pragma unroll
            for (int k = 0; k < 9; k++) acc[p][k] = 0.f;

        // Software pipeline: z(i) in buf(i&1); iter i: write z(i+1), mma(i), barrier.
        CZ(0, 0, 0, 0, zb0);
        __syncthreads();
        CZ(1, 0, 1, 1, zb1);   MP(0, 0, 0, 0, zb0);  __syncthreads();
        CZ(2, 0, 2, 2, zb0);   MP(1, 0, 1, 1, zb1);  __syncthreads();
        CZ(3, 1, 0, 1, zb1);   MP(2, 0, 2, 2, zb0);  __syncthreads();
        CZ(4, 1, 1, 0, zb0);   MP(3, 1, 0, 1, zb1);  __syncthreads();
        CZ(5, 1, 1, 2, zb1);   MP(4, 1, 1, 0, zb0);  __syncthreads();
        CZ(6, 1, 2, 1, zb0);   MP(5, 1, 1, 2, zb1);  __syncthreads();
        CZ(7, 2, 0, 2, zb1);   MP(6, 1, 2, 1, zb0);  __syncthreads();
        CZ(8, 2, 1, 1, zb0);   MP(7, 2, 0, 2, zb1);  __syncthreads();
        CZ(9, 2, 2, 0, zb1);   MP(8, 2, 1, 1, zb0);  __syncthreads();
        CZ(10, 2, 2, 2, zb0);  MP(9, 2, 2, 0, zb1);  __syncthreads();
        MP(10, 2, 2, 2, zb0);

        // Raw partial accumulation into g_agg.
#pragma unroll
        for (int p = 0; p < 4; p++) {
            int e = (p & 2) ? er1 : er0;
            int wcol = (p & 1) ? wc1 : wc0;
            if (e0 + e >= E) continue;
            int node = srcdst[64 + e];
            float* op = g_agg + node * 288;
            float* ac = acc[p];
            atomicAdd(op + wcol, ac[0]);
#pragma unroll
            for (int k = 0; k < 3; k++) atomicAdd(op + 32 + wcol * 3 + k, ac[1 + k]);
#pragma unroll
            for (int k = 0; k < 5; k++) atomicAdd(op + 128 + wcol * 5 + k, ac[4 + k]);
        }
    }
}

// ======================= final: out = agg/sqrt(10) + self-connection; re-zero agg ==========
__global__ void final_kernel(const float* __restrict__ nf, const float* __restrict__ w0,
                             const float* __restrict__ w1, const float* __restrict__ w2,
                             float* __restrict__ out) {
    __shared__ float xrow[288];
    int n = blockIdx.x;
    int t = threadIdx.x;
    xrow[t] = nf[n * 288 + t];
    __syncthreads();
    int O, d, wch, k;
    const float* W;
    if (t < 32)       { O = 0;   d = 1; wch = t;          k = 0;            W = w0; }
    else if (t < 128) { int r = t - 32;  O = 32;  d = 3; wch = r / 3; k = r - wch * 3; W = w1; }
    else              { int r = t - 128; O = 128; d = 5; wch = r / 5; k = r - wch * 5; W = w2; }
    float a = 0.f;
#pragma unroll
    for (int u = 0; u < 32; u++) a += xrow[O + u * d + k] * W[u * 32 + wch];
    int oidx = n * 288 + t;
    float agg = g_agg[oidx];
    g_agg[oidx] = 0.f;  // reset for next graph replay
    out[oidx] = agg * 0.31622776601683794f + a * 0.17677669529663687f;
}

// ======================= host: numpy RandomState(0) SILU_CST reproduction =======================
namespace {
struct NpRng {
    uint32_t mt[624];
    int mti;
    bool has_g;
    double g;
};
inline void rng_seed(NpRng& s, uint32_t sd) {
    s.mt[0] = sd;
    for (int i = 1; i < 624; i++)
        s.mt[i] = 1812433253u * (s.mt[i - 1] ^ (s.mt[i - 1] >> 30)) + (uint32_t)i;
    s.mti = 624;
    s.has_g = false;
    s.g = 0.0;
}
inline uint32_t rng_u32(NpRng& s) {
    if (s.mti >= 624) {
        for (int i = 0; i < 624; i++) {
            uint32_t y = (s.mt[i] & 0x80000000u) | (s.mt[(i + 1) % 624] & 0x7fffffffu);
            s.mt[i] = s.mt[(i + 397) % 624] ^ (y >> 1) ^ ((y & 1u) ? 0x9908b0dfu : 0u);
        }
        s.mti = 0;
    }
    uint32_t y = s.mt[s.mti++];
    y ^= y >> 11;
    y ^= (y << 7) & 0x9d2c5680u;
    y ^= (y << 15) & 0xefc60000u;
    y ^= y >> 18;
    return y;
}
inline double rng_double(NpRng& s) {
    uint32_t a = rng_u32(s) >> 5;
    uint32_t b = rng_u32(s) >> 6;
    return ((double)a * 67108864.0 + (double)b) / 9007199254740992.0;
}
inline double rng_gauss(NpRng& s) {
    if (s.has_g) {
        s.has_g = false;
        return s.g;
    }
    double x1, x2, r2;
    do {
        x1 = 2.0 * rng_double(s) - 1.0;
        x2 = 2.0 * rng_double(s) - 1.0;
        r2 = x1 * x1 + x2 * x2;
    } while (r2 >= 1.0 || r2 == 0.0);
    double f = sqrt(-2.0 * log(r2) / r2);
    s.g = f * x1;
    s.has_g = true;
    return f * x2;
}
inline double compute_silu_cst() {
    NpRng s;
    rng_seed(s, 0u);
    double sum = 0.0;
    for (int i = 0; i < 1000000; i++) {
        double z = rng_gauss(s);
        double sl = z / (1.0 + exp(-z));
        sum += sl * sl;
    }
    return 1.0 / sqrt(sum / 1000000.0);
}
}  // namespace

// ======================= launch =======================
extern "C" void kernel_launch(void* const* d_in, const int* in_sizes, int n_in,
                              void* d_out, int out_size) {
    const float* nf     = (const float*)d_in[0];
    const int*   ei     = (const int*)d_in[1];
    const float* sh     = (const float*)d_in[2];
    const float* radial = (const float*)d_in[3];
    const float* W1     = (const float*)d_in[4];
    const float* W2     = (const float*)d_in[5];
    const float* Wsc0   = (const float*)d_in[6];
    const float* Wsc1   = (const float*)d_in[7];
    const float* Wsc2   = (const float*)d_in[8];
    float* out = (float*)d_out;
    int N = in_sizes[0] / 288;
    int E = in_sizes[1] / 2;

    float cst = (float)compute_silu_cst();

    const size_t SMEM = (144 * EPAD + TEDGE * 32 + 2 * 16 * 5 * EPAD + 9 * EPAD + 1375) * 4
                        + 128 * 4;  // ~96 KB
    cudaFuncSetAttribute(msg_kernel, cudaFuncAttributeMaxDynamicSharedMemorySize, (int)SMEM);

    int ntiles = (E + TEDGE - 1) / TEDGE;
    int nunits = ntiles * 2;
    int nb = nunits < 296 ? nunits : 296;

    w3j_setup_kernel<<<11, 128>>>();
    w2h_kernel<<<(64 * 11264 + 255) / 256, 256>>>(W2);
    h_kernel<<<(E + 3) / 4, 256>>>(radial, W1, cst, E);
    msg_kernel<<<nb, NTHR, SMEM>>>(nf, ei, sh, E, nunits);
    final_kernel<<<N, 288>>>(nf, Wsc0, Wsc1, Wsc2, out);
}

// round 15
// speedup vs baseline: 1.2223x; 1.2223x over previous
#include <cuda_runtime.h>
#include <cuda_fp16.h>
#include <math.h>
#include <stdint.h>

#define NTHR 256
#define TEDGE 32
#define EPAD 33

// ---------------- device scratch (static, no allocation) ----------------
__device__ float g_w3j[11 * 125];        // per-instruction wigner3j, pre-scaled by PW[l3]
__device__ uint4 g_W2H[11 * 32 * 4 * 2 * 32];  // W2 in fp16 B-fragment layout (1.44 MB)
__device__ __half g_Hh[20000 * 64];      // weight-NN hidden activations (fp16)
__device__ float g_agg[2048 * 288];      // message aggregation buffer (zeroed by final_kernel)

// irrep constants
constexpr int DIMS_[3] = {1, 3, 5};
constexpr int OFF_[3]  = {0, 32, 128};  // offsets into 288-dim feature
constexpr int SO_[3]   = {0, 1, 4};     // offsets into 9-dim sh
constexpr int KO_[3]   = {0, 1, 4};     // offsets into 9-slot accumulator

// fp16 m16n8k16 MMA, D += A*B (fp32 accumulate)
__device__ __forceinline__ void mma_f16(float* d, const uint32_t* a, uint32_t b0, uint32_t b1) {
    asm volatile(
        "mma.sync.aligned.m16n8k16.row.col.f32.f16.f16.f32 "
        "{%0,%1,%2,%3}, {%4,%5,%6,%7}, {%8,%9}, {%0,%1,%2,%3};\n"
        : "+f"(d[0]), "+f"(d[1]), "+f"(d[2]), "+f"(d[3])
        : "r"(a[0]), "r"(a[1]), "r"(a[2]), "r"(a[3]), "r"(b0), "r"(b1));
}

// ======================= wigner-3j setup (reference algorithm) =======================
__device__ __forceinline__ double dfact(int n) {
    double r = 1.0;
    for (int i = 2; i <= n; i++) r *= (double)i;
    return r;
}

__device__ void build_q(int l, double* qr, double* qi) {
    int D = 2 * l + 1;
    for (int i = 0; i < D * D; i++) { qr[i] = 0.0; qi[i] = 0.0; }
    const double s2 = 0.70710678118654752440;
    for (int m = -l; m < 0; m++) {
        qr[(l + m) * D + (l - m)] = s2;
        qi[(l + m) * D + (l + m)] = -s2;
    }
    qr[l * D + l] = 1.0;
    for (int m = 1; m <= l; m++) {
        double sg = (m & 1) ? -1.0 : 1.0;
        qr[(l + m) * D + (l + m)] = sg * s2;
        qi[(l + m) * D + (l - m)] = sg * s2;
    }
    double fr, fi;
    switch (l & 3) {
        case 0: fr = 1;  fi = 0;  break;
        case 1: fr = 0;  fi = -1; break;
        case 2: fr = -1; fi = 0;  break;
        default: fr = 0; fi = 1;  break;
    }
    for (int i = 0; i < D * D; i++) {
        double r = qr[i], im = qi[i];
        qr[i] = r * fr - im * fi;
        qi[i] = r * fi + im * fr;
    }
}

__global__ void w3j_setup_kernel() {
    const int L1[11] = {0, 0, 0, 1, 1, 1, 1, 2, 2, 2, 2};
    const int L2[11] = {0, 1, 2, 0, 1, 1, 2, 0, 1, 2, 2};
    const int L3[11] = {0, 1, 2, 1, 0, 2, 1, 2, 1, 0, 2};
    int t = blockIdx.x;
    int j1 = L1[t], j2 = L2[t], j3 = L3[t];
    int d1 = 2 * j1 + 1, d2 = 2 * j2 + 1, d3 = 2 * j3 + 1;
    __shared__ double Cs[125];
    __shared__ double Q1r[25], Q1i[25], Q2r[25], Q2i[25], Q3r[25], Q3i[25];
    __shared__ double outv[125];
    __shared__ double scale_s;
    int tid = threadIdx.x;
    if (tid < 125) Cs[tid] = 0.0;
    if (tid == 0) {
        build_q(j1, Q1r, Q1i);
        build_q(j2, Q2r, Q2i);
        build_q(j3, Q3r, Q3i);
    }
    __syncthreads();
    if (tid < d1 * d2) {
        int m1 = tid / d2 - j1;
        int m2 = tid % d2 - j2;
        int m3 = m1 + m2;
        if (m3 >= -j3 && m3 <= j3) {
            int vmin = -j1 + j2 + m3;
            if (-j1 + m1 > vmin) vmin = -j1 + m1;
            if (vmin < 0) vmin = 0;
            int vmax = j2 + j3 + m1;
            if (j3 - j1 + j2 < vmax) vmax = j3 - j1 + j2;
            if (j3 + m3 < vmax) vmax = j3 + m3;
            double c = sqrt((double)(2 * j3 + 1) * dfact(j3 + j1 - j2) * dfact(j3 - j1 + j2) *
                            dfact(j1 + j2 - j3) * dfact(j3 + m3) * dfact(j3 - m3) /
                            (dfact(j1 + j2 + j3 + 1) * dfact(j1 - m1) * dfact(j1 + m1) *
                             dfact(j2 - m2) * dfact(j2 + m2)));
            double s = 0.0;
            for (int v = vmin; v <= vmax; v++) {
                double term = dfact(j2 + j3 + m1 - v) * dfact(j1 - m1 + v) /
                              (dfact(v) * dfact(j3 - j1 + j2 - v) * dfact(j3 + m3 - v) *
                               dfact(v + j1 - j2 - m3));
                if ((v + j2 + m2) & 1) term = -term;
                s += term;
            }
            Cs[((m1 + j1) * d2 + (m2 + j2)) * d3 + (m3 + j3)] = c * s;
        }
    }
    __syncthreads();
    int nel = d1 * d2 * d3;
    if (tid < nel) {
        int jj = tid / (d2 * d3);
        int ll = (tid / d3) % d2;
        int mm = tid % d3;
        double ar = 0.0;
        for (int i = 0; i < d1; i++)
            for (int k = 0; k < d2; k++)
                for (int n = 0; n < d3; n++) {
                    double cv = Cs[(i * d2 + k) * d3 + n];
                    if (cv == 0.0) continue;
                    double p1r = Q1r[i * d1 + jj], p1i = Q1i[i * d1 + jj];
                    double p2r = Q2r[k * d2 + ll], p2i = Q2i[k * d2 + ll];
                    double p3r = Q3r[n * d3 + mm], p3i = -Q3i[n * d3 + mm];
                    double t1r = p1r * p2r - p1i * p2i;
                    double t1i = p1r * p2i + p1i * p2r;
                    double t2r = t1r * p3r - t1i * p3i;
                    ar += t2r * cv;
                }
        outv[tid] = ar;
    }
    __syncthreads();
    if (tid == 0) {
        const double PWv[3] = {0.10206207261596575, 0.15309310892394862, 0.19764235376052370};
        double s = 0.0;
        for (int i = 0; i < nel; i++) s += outv[i] * outv[i];
        scale_s = PWv[j3] / sqrt(s);
    }
    __syncthreads();
    if (tid < nel) g_w3j[t * 125 + tid] = (float)(outv[tid] * scale_s);
}

// ======================= W2 relayout into fp16 B-fragment order =======================
__global__ void w2h_kernel(const float* __restrict__ W2) {
    int idx = blockIdx.x * 256 + threadIdx.x;
    if (idx >= 64 * 11264) return;
    int c = idx / 11264;
    int col = idx - c * 11264;
    int ins = col >> 10;
    int rem = col & 1023;
    int u = rem >> 5;
    int w = rem & 31;
    int wtile = w >> 3, n = w & 7;
    int q = c >> 4, cl = c & 15;
    int hsel = cl >> 3;
    int c8 = cl & 7;
    int tig = c8 >> 1, pp = c8 & 1;
    int lane = (n << 2) | tig;
    int q2 = q >> 1, qq = q & 1;
    int u4 = (((ins * 32 + u) * 4 + wtile) * 2 + q2) * 32 + lane;
    int hidx = u4 * 8 + (qq * 2 + hsel) * 2 + pp;
    ((__half*)g_W2H)[hidx] = __float2half(W2[idx] * 0.125f);
}

// ======================= weight-NN hidden layer (fp16 output) =======================
__global__ void h_kernel(const float* __restrict__ radial, const float* __restrict__ W1,
                         float cst, int E) {
    __shared__ float rs[4][64];
    int le = threadIdx.x >> 6, c = threadIdx.x & 63;
    int e = blockIdx.x * 4 + le;
    rs[le][c] = (e < E) ? radial[e * 64 + c] : 0.f;
    __syncthreads();
    float a = 0.f;
#pragma unroll
    for (int r = 0; r < 64; r++) a += rs[le][r] * W1[r * 64 + c];
    a *= 0.125f;  // 1/sqrt(64)
    float hv = cst * a / (1.f + expf(-a));
    if (e < E) g_Hh[e * 64 + c] = __float2half(hv);
}

// ======================= fused message kernel (persistent, 2 blocks/SM) ==========
// Work unit = 32-edge tile, full u-range. Block = 256 threads = 8 warps.
// Warp wid: wtile = wid&3, rtile = wid>>2 (0..1). Warp: 16 edges x 8 w-cols.
// 2 blocks/SM: independent barriers overlap stalls across blocks.

// z computation with fused s: thread owns edge e = tid&31, u = (tid>>5) + s*8, s<4.
template <int D1, int D2, int D3, int SO2, int O1, int W3OFF>
__device__ __forceinline__ void compute_z(const float* __restrict__ xs,
                                          float* __restrict__ zb,
                                          const float* __restrict__ shT,
                                          const float* __restrict__ w3j_s, int tid) {
    int e = tid & 31;
    int u0 = tid >> 5;  // 0..7
    float shv[D2];
#pragma unroll
    for (int j = 0; j < D2; j++) shv[j] = shT[(SO2 + j) * EPAD + e];
    float sv[D1 * D3];
#pragma unroll
    for (int i = 0; i < D1; i++)
#pragma unroll
        for (int k = 0; k < D3; k++) {
            float a = 0.f;
#pragma unroll
            for (int j = 0; j < D2; j++)
                a += w3j_s[W3OFF + (i * D2 + j) * D3 + k] * shv[j];
            sv[i * D3 + k] = a;
        }
#pragma unroll
    for (int s = 0; s < 4; s++) {
        int u = u0 + s * 8;
        float xv[D1];
#pragma unroll
        for (int i = 0; i < D1; i++) xv[i] = xs[(O1 + u * D1 + i) * EPAD + e];
#pragma unroll
        for (int k = 0; k < D3; k++) {
            float z = 0.f;
#pragma unroll
            for (int i = 0; i < D1; i++) z += xv[i] * sv[i * D3 + k];
            zb[(u * D3 + k) * EPAD + e] = z;
        }
    }
}

// Consume one u: 4 MMAs (2 independent chains) + z-weighted accumulation.
template <int D3, int KO>
__device__ __forceinline__ void consume_u(const float* __restrict__ zb,
                                          const uint32_t (&af)[4][4], float (&acc)[4][9],
                                          int u, int er0, int er1,
                                          const uint4& Ba, const uint4& Bb) {
    float c0[4] = {0.f, 0.f, 0.f, 0.f};
    float c1[4] = {0.f, 0.f, 0.f, 0.f};
    mma_f16(c0, af[0], Ba.x, Ba.y);
    mma_f16(c1, af[1], Ba.z, Ba.w);
    mma_f16(c0, af[2], Bb.x, Bb.y);
    mma_f16(c1, af[3], Bb.z, Bb.w);
    float wv0 = c0[0] + c1[0];
    float wv1 = c0[1] + c1[1];
    float wv2 = c0[2] + c1[2];
    float wv3 = c0[3] + c1[3];
#pragma unroll
    for (int k = 0; k < D3; k++) {
        float z0 = zb[(u * D3 + k) * EPAD + er0];
        float z1 = zb[(u * D3 + k) * EPAD + er1];
        acc[0][KO + k] += wv0 * z0;
        acc[1][KO + k] += wv1 * z0;
        acc[2][KO + k] += wv2 * z1;
        acc[3][KO + k] += wv3 * z1;
    }
}

// MMA phase for one ins: unroll-4 register rotation, depth-4 B prefetch.
template <int D3, int KO, int PB>
__device__ __forceinline__ void mma_phase(const float* __restrict__ zb,
                                          const uint32_t (&af)[4][4], float (&acc)[4][9],
                                          int lane, int wtile, int er0, int er1) {
    const uint4* __restrict__ Bp = g_W2H + PB + wtile * 64 + lane;
    uint4 s0a = __ldg(Bp +   0), s0b = __ldg(Bp +  32);   // u=0
    uint4 s1a = __ldg(Bp + 256), s1b = __ldg(Bp + 288);   // u=1
    uint4 s2a = __ldg(Bp + 512), s2b = __ldg(Bp + 544);   // u=2
    uint4 s3a = __ldg(Bp + 768), s3b = __ldg(Bp + 800);   // u=3
#pragma unroll 1
    for (int ub = 0; ub < 32; ub += 4) {
        bool more = ub < 28;
        consume_u<D3, KO>(zb, af, acc, ub + 0, er0, er1, s0a, s0b);
        if (more) { const uint4* B = Bp + (ub + 4) * 256; s0a = __ldg(B); s0b = __ldg(B + 32); }
        consume_u<D3, KO>(zb, af, acc, ub + 1, er0, er1, s1a, s1b);
        if (more) { const uint4* B = Bp + (ub + 5) * 256; s1a = __ldg(B); s1b = __ldg(B + 32); }
        consume_u<D3, KO>(zb, af, acc, ub + 2, er0, er1, s2a, s2b);
        if (more) { const uint4* B = Bp + (ub + 6) * 256; s2a = __ldg(B); s2b = __ldg(B + 32); }
        consume_u<D3, KO>(zb, af, acc, ub + 3, er0, er1, s3a, s3b);
        if (more) { const uint4* B = Bp + (ub + 7) * 256; s3a = __ldg(B); s3b = __ldg(B + 32); }
    }
}

// per-ins template args: A=i1, B=i2, C=i3
#define CZ(IDX, A, B, Cc, BUF)                                                          \
    compute_z<DIMS_[A], DIMS_[B], DIMS_[Cc], SO_[B], OFF_[A], IDX * 125>(               \
        xs, BUF, shT, w3j_s, tid)
#define MP(IDX, A, B, Cc, BUF)                                                          \
    mma_phase<DIMS_[Cc], KO_[Cc], IDX * 8192>(BUF, af, acc, lane, wtile, er0, er1)

__global__ void __launch_bounds__(NTHR, 2)
msg_kernel(const float* __restrict__ nf, const int* __restrict__ ei,
           const float* __restrict__ shg, int E, int nunits) {
    extern __shared__ float smem[];
    float* xs    = smem;                          // 288*33 = 9504
    __half* hsm  = (__half*)(xs + 288 * EPAD);    // 32*64 halves (1024 floats)
    float* zb0   = xs + 288 * EPAD + TEDGE * 32;  // 32*5*33 = 5280
    float* zb1   = zb0 + 32 * 5 * EPAD;           // 32*5*33
    float* shT   = zb1 + 32 * 5 * EPAD;           // 9*33 = 297
    float* w3j_s = shT + 9 * EPAD;                // 1375
    int* srcdst  = (int*)(w3j_s + 1375);          // 64 ints
    int tid = threadIdx.x;

    // loop-invariant: w3j table (visibility covered by loop-top barrier)
    for (int idx = tid; idx < 11 * 125; idx += NTHR) w3j_s[idx] = g_w3j[idx];

    int lane = tid & 31;
    int wid = tid >> 5;
    int rtile = wid >> 2, wtile = wid & 3;
    int g = lane >> 2, tig = lane & 3;
    int er0 = rtile * 16 + g, er1 = er0 + 8;
    int wc0 = wtile * 8 + 2 * tig, wc1 = wc0 + 1;
    const uint32_t* hs2 = (const uint32_t*)hsm;

    for (int tile = blockIdx.x; tile < nunits; tile += gridDim.x) {
        int e0 = tile * TEDGE;
        __syncthreads();  // previous unit's smem readers done (and w3j_s visible, 1st iter)

        if (tid < 64) {
            int e = e0 + (tid & 31);
            int which = tid >> 5;
            srcdst[tid] = (e < E) ? ei[which * E + e] : 0;
        }
        __syncthreads();
        for (int idx = tid; idx < TEDGE * 288; idx += NTHR) {
            int e = idx / 288;
            int c = idx - e * 288;
            xs[c * EPAD + e] = (e0 + e < E) ? nf[srcdst[e] * 288 + c] : 0.f;
        }
        for (int idx = tid; idx < TEDGE * 64; idx += NTHR) {
            int e = idx >> 6;
            int c = idx & 63;
            hsm[e * 64 + c] = (e0 + e < E) ? g_Hh[(e0 + e) * 64 + c] : __float2half(0.f);
        }
        for (int idx = tid; idx < TEDGE * 9; idx += NTHR) {
            int e = idx & 31;
            int j = idx >> 5;
            shT[j * EPAD + e] = (e0 + e < E) ? shg[(e0 + e) * 9 + j] : 0.f;
        }
        __syncthreads();  // hsm/xs/shT ready

        // A fragments (h, fp16 half2-packed)
        uint32_t af[4][4];
#pragma unroll
        for (int q = 0; q < 4; q++) {
            af[q][0] = hs2[er0 * 32 + q * 8 + tig];
            af[q][1] = hs2[er1 * 32 + q * 8 + tig];
            af[q][2] = hs2[er0 * 32 + q * 8 + 4 + tig];
            af[q][3] = hs2[er1 * 32 + q * 8 + 4 + tig];
        }

        float acc[4][9];
#pragma unroll
        for (int p = 0; p < 4; p++)
#pragma unroll
            for (int k = 0; k < 9; k++) acc[p][k] = 0.f;

        // Software pipeline: z(i) in buf(i&1); iter i: write z(i+1), mma(i), barrier.
        CZ(0, 0, 0, 0, zb0);
        __syncthreads();
        CZ(1, 0, 1, 1, zb1);   MP(0, 0, 0, 0, zb0);  __syncthreads();
        CZ(2, 0, 2, 2, zb0);   MP(1, 0, 1, 1, zb1);  __syncthreads();
        CZ(3, 1, 0, 1, zb1);   MP(2, 0, 2, 2, zb0);  __syncthreads();
        CZ(4, 1, 1, 0, zb0);   MP(3, 1, 0, 1, zb1);  __syncthreads();
        CZ(5, 1, 1, 2, zb1);   MP(4, 1, 1, 0, zb0);  __syncthreads();
        CZ(6, 1, 2, 1, zb0);   MP(5, 1, 1, 2, zb1);  __syncthreads();
        CZ(7, 2, 0, 2, zb1);   MP(6, 1, 2, 1, zb0);  __syncthreads();
        CZ(8, 2, 1, 1, zb0);   MP(7, 2, 0, 2, zb1);  __syncthreads();
        CZ(9, 2, 2, 0, zb1);   MP(8, 2, 1, 1, zb0);  __syncthreads();
        CZ(10, 2, 2, 2, zb0);  MP(9, 2, 2, 0, zb1);  __syncthreads();
        MP(10, 2, 2, 2, zb0);

        // Raw accumulation into g_agg (final_kernel applies 1/sqrt(10) + self-connection).
#pragma unroll
        for (int p = 0; p < 4; p++) {
            int e = (p & 2) ? er1 : er0;
            int wcol = (p & 1) ? wc1 : wc0;
            if (e0 + e >= E) continue;
            int node = srcdst[32 + e];
            float* op = g_agg + node * 288;
            float* ac = acc[p];
            atomicAdd(op + wcol, ac[0]);
#pragma unroll
            for (int k = 0; k < 3; k++) atomicAdd(op + 32 + wcol * 3 + k, ac[1 + k]);
#pragma unroll
            for (int k = 0; k < 5; k++) atomicAdd(op + 128 + wcol * 5 + k, ac[4 + k]);
        }
    }
}

// ======================= final: out = agg/sqrt(10) + self-connection; re-zero agg ==========
__global__ void final_kernel(const float* __restrict__ nf, const float* __restrict__ w0,
                             const float* __restrict__ w1, const float* __restrict__ w2,
                             float* __restrict__ out) {
    __shared__ float xrow[288];
    int n = blockIdx.x;
    int t = threadIdx.x;
    xrow[t] = nf[n * 288 + t];
    __syncthreads();
    int O, d, wch, k;
    const float* W;
    if (t < 32)       { O = 0;   d = 1; wch = t;          k = 0;            W = w0; }
    else if (t < 128) { int r = t - 32;  O = 32;  d = 3; wch = r / 3; k = r - wch * 3; W = w1; }
    else              { int r = t - 128; O = 128; d = 5; wch = r / 5; k = r - wch * 5; W = w2; }
    float a = 0.f;
#pragma unroll
    for (int u = 0; u < 32; u++) a += xrow[O + u * d + k] * W[u * 32 + wch];
    int oidx = n * 288 + t;
    float agg = g_agg[oidx];
    g_agg[oidx] = 0.f;  // reset for next graph replay
    out[oidx] = agg * 0.31622776601683794f + a * 0.17677669529663687f;
}

// ======================= host: numpy RandomState(0) SILU_CST reproduction =======================
namespace {
struct NpRng {
    uint32_t mt[624];
    int mti;
    bool has_g;
    double g;
};
inline void rng_seed(NpRng& s, uint32_t sd) {
    s.mt[0] = sd;
    for (int i = 1; i < 624; i++)
        s.mt[i] = 1812433253u * (s.mt[i - 1] ^ (s.mt[i - 1] >> 30)) + (uint32_t)i;
    s.mti = 624;
    s.has_g = false;
    s.g = 0.0;
}
inline uint32_t rng_u32(NpRng& s) {
    if (s.mti >= 624) {
        for (int i = 0; i < 624; i++) {
            uint32_t y = (s.mt[i] & 0x80000000u) | (s.mt[(i + 1) % 624] & 0x7fffffffu);
            s.mt[i] = s.mt[(i + 397) % 624] ^ (y >> 1) ^ ((y & 1u) ? 0x9908b0dfu : 0u);
        }
        s.mti = 0;
    }
    uint32_t y = s.mt[s.mti++];
    y ^= y >> 11;
    y ^= (y << 7) & 0x9d2c5680u;
    y ^= (y << 15) & 0xefc60000u;
    y ^= y >> 18;
    return y;
}
inline double rng_double(NpRng& s) {
    uint32_t a = rng_u32(s) >> 5;
    uint32_t b = rng_u32(s) >> 6;
    return ((double)a * 67108864.0 + (double)b) / 9007199254740992.0;
}
inline double rng_gauss(NpRng& s) {
    if (s.has_g) {
        s.has_g = false;
        return s.g;
    }
    double x1, x2, r2;
    do {
        x1 = 2.0 * rng_double(s) - 1.0;
        x2 = 2.0 * rng_double(s) - 1.0;
        r2 = x1 * x1 + x2 * x2;
    } while (r2 >= 1.0 || r2 == 0.0);
    double f = sqrt(-2.0 * log(r2) / r2);
    s.g = f * x1;
    s.has_g = true;
    return f * x2;
}
inline double compute_silu_cst() {
    NpRng s;
    rng_seed(s, 0u);
    double sum = 0.0;
    for (int i = 0; i < 1000000; i++) {
        double z = rng_gauss(s);
        double sl = z / (1.0 + exp(-z));
        sum += sl * sl;
    }
    return 1.0 / sqrt(sum / 1000000.0);
}
}  // namespace

// ======================= launch =======================
extern "C" void kernel_launch(void* const* d_in, const int* in_sizes, int n_in,
                              void* d_out, int out_size) {
    const float* nf     = (const float*)d_in[0];
    const int*   ei     = (const int*)d_in[1];
    const float* sh     = (const float*)d_in[2];
    const float* radial = (const float*)d_in[3];
    const float* W1     = (const float*)d_in[4];
    const float* W2     = (const float*)d_in[5];
    const float* Wsc0   = (const float*)d_in[6];
    const float* Wsc1   = (const float*)d_in[7];
    const float* Wsc2   = (const float*)d_in[8];
    float* out = (float*)d_out;
    int N = in_sizes[0] / 288;
    int E = in_sizes[1] / 2;

    float cst = (float)compute_silu_cst();

    const size_t SMEM = (288 * EPAD + TEDGE * 32 + 2 * 32 * 5 * EPAD + 9 * EPAD + 1375) * 4
                        + 64 * 4;  // ~91 KB -> 2 blocks/SM
    cudaFuncSetAttribute(msg_kernel, cudaFuncAttributeMaxDynamicSharedMemorySize, (int)SMEM);

    int ntiles = (E + TEDGE - 1) / TEDGE;        // 625
    int nb = ntiles < 592 ? ntiles : 592;        // 2 blocks/SM x 148 SMs x 2 waves

    w3j_setup_kernel<<<11, 128>>>();
    w2h_kernel<<<(64 * 11264 + 255) / 256, 256>>>(W2);
    h_kernel<<<(E + 3) / 4, 256>>>(radial, W1, cst, E);
    msg_kernel<<<nb, NTHR, SMEM>>>(nf, ei, sh, E, ntiles);
    final_kernel<<<N, 288>>>(nf, Wsc0, Wsc1, Wsc2, out);
}

// round 16
// speedup vs baseline: 1.2907x; 1.0559x over previous
#include <cuda_runtime.h>
#include <cuda_fp16.h>
#include <math.h>
#include <stdint.h>

#define NTHR 256
#define TEDGE 32
#define EPAD 33

// ---------------- device scratch (static, no allocation) ----------------
__device__ float g_w3j[11 * 125];        // per-instruction wigner3j, pre-scaled by PW[l3]
__device__ uint4 g_W2H[11 * 32 * 4 * 2 * 32];  // W2 in fp16 B-fragment layout (1.44 MB)
__device__ __half g_Hh[20000 * 64];      // weight-NN hidden activations (fp16)
__device__ float g_agg[2048 * 288];      // message aggregation buffer (zeroed by final_kernel)

// irrep constants
constexpr int DIMS_[3] = {1, 3, 5};
constexpr int OFF_[3]  = {0, 32, 128};  // offsets into 288-dim feature
constexpr int SO_[3]   = {0, 1, 4};     // offsets into 9-dim sh
constexpr int KO_[3]   = {0, 1, 4};     // offsets into 9-slot accumulator

// fp16 m16n8k16 MMA, D += A*B (fp32 accumulate)
__device__ __forceinline__ void mma_f16(float* d, const uint32_t* a, uint32_t b0, uint32_t b1) {
    asm volatile(
        "mma.sync.aligned.m16n8k16.row.col.f32.f16.f16.f32 "
        "{%0,%1,%2,%3}, {%4,%5,%6,%7}, {%8,%9}, {%0,%1,%2,%3};\n"
        : "+f"(d[0]), "+f"(d[1]), "+f"(d[2]), "+f"(d[3])
        : "r"(a[0]), "r"(a[1]), "r"(a[2]), "r"(a[3]), "r"(b0), "r"(b1));
}

// ======================= wigner-3j setup (reference algorithm) =======================
__device__ __forceinline__ double dfact(int n) {
    double r = 1.0;
    for (int i = 2; i <= n; i++) r *= (double)i;
    return r;
}

__device__ void build_q(int l, double* qr, double* qi) {
    int D = 2 * l + 1;
    for (int i = 0; i < D * D; i++) { qr[i] = 0.0; qi[i] = 0.0; }
    const double s2 = 0.70710678118654752440;
    for (int m = -l; m < 0; m++) {
        qr[(l + m) * D + (l - m)] = s2;
        qi[(l + m) * D + (l + m)] = -s2;
    }
    qr[l * D + l] = 1.0;
    for (int m = 1; m <= l; m++) {
        double sg = (m & 1) ? -1.0 : 1.0;
        qr[(l + m) * D + (l + m)] = sg * s2;
        qi[(l + m) * D + (l - m)] = sg * s2;
    }
    double fr, fi;
    switch (l & 3) {
        case 0: fr = 1;  fi = 0;  break;
        case 1: fr = 0;  fi = -1; break;
        case 2: fr = -1; fi = 0;  break;
        default: fr = 0; fi = 1;  break;
    }
    for (int i = 0; i < D * D; i++) {
        double r = qr[i], im = qi[i];
        qr[i] = r * fr - im * fi;
        qi[i] = r * fi + im * fr;
    }
}

__global__ void w3j_setup_kernel() {
    const int L1[11] = {0, 0, 0, 1, 1, 1, 1, 2, 2, 2, 2};
    const int L2[11] = {0, 1, 2, 0, 1, 1, 2, 0, 1, 2, 2};
    const int L3[11] = {0, 1, 2, 1, 0, 2, 1, 2, 1, 0, 2};
    int t = blockIdx.x;
    int j1 = L1[t], j2 = L2[t], j3 = L3[t];
    int d1 = 2 * j1 + 1, d2 = 2 * j2 + 1, d3 = 2 * j3 + 1;
    __shared__ double Cs[125];
    __shared__ double Q1r[25], Q1i[25], Q2r[25], Q2i[25], Q3r[25], Q3i[25];
    __shared__ double outv[125];
    __shared__ double scale_s;
    int tid = threadIdx.x;
    if (tid < 125) Cs[tid] = 0.0;
    if (tid == 0) {
        build_q(j1, Q1r, Q1i);
        build_q(j2, Q2r, Q2i);
        build_q(j3, Q3r, Q3i);
    }
    __syncthreads();
    if (tid < d1 * d2) {
        int m1 = tid / d2 - j1;
        int m2 = tid % d2 - j2;
        int m3 = m1 + m2;
        if (m3 >= -j3 && m3 <= j3) {
            int vmin = -j1 + j2 + m3;
            if (-j1 + m1 > vmin) vmin = -j1 + m1;
            if (vmin < 0) vmin = 0;
            int vmax = j2 + j3 + m1;
            if (j3 - j1 + j2 < vmax) vmax = j3 - j1 + j2;
            if (j3 + m3 < vmax) vmax = j3 + m3;
            double c = sqrt((double)(2 * j3 + 1) * dfact(j3 + j1 - j2) * dfact(j3 - j1 + j2) *
                            dfact(j1 + j2 - j3) * dfact(j3 + m3) * dfact(j3 - m3) /
                            (dfact(j1 + j2 + j3 + 1) * dfact(j1 - m1) * dfact(j1 + m1) *
                             dfact(j2 - m2) * dfact(j2 + m2)));
            double s = 0.0;
            for (int v = vmin; v <= vmax; v++) {
                double term = dfact(j2 + j3 + m1 - v) * dfact(j1 - m1 + v) /
                              (dfact(v) * dfact(j3 - j1 + j2 - v) * dfact(j3 + m3 - v) *
                               dfact(v + j1 - j2 - m3));
                if ((v + j2 + m2) & 1) term = -term;
                s += term;
            }
            Cs[((m1 + j1) * d2 + (m2 + j2)) * d3 + (m3 + j3)] = c * s;
        }
    }
    __syncthreads();
    int nel = d1 * d2 * d3;
    if (tid < nel) {
        int jj = tid / (d2 * d3);
        int ll = (tid / d3) % d2;
        int mm = tid % d3;
        double ar = 0.0;
        for (int i = 0; i < d1; i++)
            for (int k = 0; k < d2; k++)
                for (int n = 0; n < d3; n++) {
                    double cv = Cs[(i * d2 + k) * d3 + n];
                    if (cv == 0.0) continue;
                    double p1r = Q1r[i * d1 + jj], p1i = Q1i[i * d1 + jj];
                    double p2r = Q2r[k * d2 + ll], p2i = Q2i[k * d2 + ll];
                    double p3r = Q3r[n * d3 + mm], p3i = -Q3i[n * d3 + mm];
                    double t1r = p1r * p2r - p1i * p2i;
                    double t1i = p1r * p2i + p1i * p2r;
                    double t2r = t1r * p3r - t1i * p3i;
                    ar += t2r * cv;
                }
        outv[tid] = ar;
    }
    __syncthreads();
    if (tid == 0) {
        const double PWv[3] = {0.10206207261596575, 0.15309310892394862, 0.19764235376052370};
        double s = 0.0;
        for (int i = 0; i < nel; i++) s += outv[i] * outv[i];
        scale_s = PWv[j3] / sqrt(s);
    }
    __syncthreads();
    if (tid < nel) g_w3j[t * 125 + tid] = (float)(outv[tid] * scale_s);
}

// ======================= W2 relayout into fp16 B-fragment order =======================
__global__ void w2h_kernel(const float* __restrict__ W2) {
    int idx = blockIdx.x * 256 + threadIdx.x;
    if (idx >= 64 * 11264) return;
    int c = idx / 11264;
    int col = idx - c * 11264;
    int ins = col >> 10;
    int rem = col & 1023;
    int u = rem >> 5;
    int w = rem & 31;
    int wtile = w >> 3, n = w & 7;
    int q = c >> 4, cl = c & 15;
    int hsel = cl >> 3;
    int c8 = cl & 7;
    int tig = c8 >> 1, pp = c8 & 1;
    int lane = (n << 2) | tig;
    int q2 = q >> 1, qq = q & 1;
    int u4 = (((ins * 32 + u) * 4 + wtile) * 2 + q2) * 32 + lane;
    int hidx = u4 * 8 + (qq * 2 + hsel) * 2 + pp;
    ((__half*)g_W2H)[hidx] = __float2half(W2[idx] * 0.125f);
}

// ======================= weight-NN hidden layer (fp16 output) =======================
__global__ void h_kernel(const float* __restrict__ radial, const float* __restrict__ W1,
                         float cst, int E) {
    __shared__ float rs[4][64];
    int le = threadIdx.x >> 6, c = threadIdx.x & 63;
    int e = blockIdx.x * 4 + le;
    rs[le][c] = (e < E) ? radial[e * 64 + c] : 0.f;
    __syncthreads();
    float a = 0.f;
#pragma unroll
    for (int r = 0; r < 64; r++) a += rs[le][r] * W1[r * 64 + c];
    a *= 0.125f;  // 1/sqrt(64)
    float hv = cst * a / (1.f + expf(-a));
    if (e < E) g_Hh[e * 64 + c] = __float2half(hv);
}

// ======================= fused message kernel (persistent, 2 blocks/SM) ==========
// Work unit = 32-edge tile. Block = 256 threads = 8 warps, 2 blocks/SM.
// z layout: pair-packed float2 — zb[(u*D3+k)*32 + eoff], eoff pairs rows (e, e+8).

// z computation with fused s: thread owns edge e = tid&31, u = (tid>>5) + s*8, s<4.
template <int D1, int D2, int D3, int SO2, int O1, int W3OFF>
__device__ __forceinline__ void compute_z(const float* __restrict__ xs,
                                          float* __restrict__ zb,
                                          const float* __restrict__ shT,
                                          const float* __restrict__ w3j_s, int tid, int eoff) {
    int e = tid & 31;
    int u0 = tid >> 5;  // 0..7
    float shv[D2];
#pragma unroll
    for (int j = 0; j < D2; j++) shv[j] = shT[(SO2 + j) * EPAD + e];
    float sv[D1 * D3];
#pragma unroll
    for (int i = 0; i < D1; i++)
#pragma unroll
        for (int k = 0; k < D3; k++) {
            float a = 0.f;
#pragma unroll
            for (int j = 0; j < D2; j++)
                a += w3j_s[W3OFF + (i * D2 + j) * D3 + k] * shv[j];
            sv[i * D3 + k] = a;
        }
#pragma unroll
    for (int s = 0; s < 4; s++) {
        int u = u0 + s * 8;
        float xv[D1];
#pragma unroll
        for (int i = 0; i < D1; i++) xv[i] = xs[(O1 + u * D1 + i) * EPAD + e];
#pragma unroll
        for (int k = 0; k < D3; k++) {
            float z = 0.f;
#pragma unroll
            for (int i = 0; i < D1; i++) z += xv[i] * sv[i * D3 + k];
            zb[(u * D3 + k) * 32 + eoff] = z;
        }
    }
}

// Consume one u: 4 serial MMAs (single chain, no merge adds) + pair-packed z loads.
template <int D3, int KO>
__device__ __forceinline__ void consume_u(const float2* __restrict__ zb2,
                                          const uint32_t (&af)[4][4], float (&acc)[4][9],
                                          int u, int zp,
                                          const uint4& Ba, const uint4& Bb) {
    float c[4] = {0.f, 0.f, 0.f, 0.f};
    mma_f16(c, af[0], Ba.x, Ba.y);
    mma_f16(c, af[1], Ba.z, Ba.w);
    mma_f16(c, af[2], Bb.x, Bb.y);
    mma_f16(c, af[3], Bb.z, Bb.w);
#pragma unroll
    for (int k = 0; k < D3; k++) {
        float2 z01 = zb2[(u * D3 + k) * 16 + zp];   // z for rows (er0, er1) in one LDS.64
        acc[0][KO + k] += c[0] * z01.x;
        acc[1][KO + k] += c[1] * z01.x;
        acc[2][KO + k] += c[2] * z01.y;
        acc[3][KO + k] += c[3] * z01.y;
    }
}

// MMA phase for one ins: unroll-4 register rotation, depth-4 B prefetch.
template <int D3, int KO, int PB>
__device__ __forceinline__ void mma_phase(const float2* __restrict__ zb2,
                                          const uint32_t (&af)[4][4], float (&acc)[4][9],
                                          int lane, int wtile, int zp) {
    const uint4* __restrict__ Bp = g_W2H + PB + wtile * 64 + lane;
    uint4 s0a = __ldg(Bp +   0), s0b = __ldg(Bp +  32);   // u=0
    uint4 s1a = __ldg(Bp + 256), s1b = __ldg(Bp + 288);   // u=1
    uint4 s2a = __ldg(Bp + 512), s2b = __ldg(Bp + 544);   // u=2
    uint4 s3a = __ldg(Bp + 768), s3b = __ldg(Bp + 800);   // u=3
#pragma unroll 1
    for (int ub = 0; ub < 32; ub += 4) {
        bool more = ub < 28;
        consume_u<D3, KO>(zb2, af, acc, ub + 0, zp, s0a, s0b);
        if (more) { const uint4* B = Bp + (ub + 4) * 256; s0a = __ldg(B); s0b = __ldg(B + 32); }
        consume_u<D3, KO>(zb2, af, acc, ub + 1, zp, s1a, s1b);
        if (more) { const uint4* B = Bp + (ub + 5) * 256; s1a = __ldg(B); s1b = __ldg(B + 32); }
        consume_u<D3, KO>(zb2, af, acc, ub + 2, zp, s2a, s2b);
        if (more) { const uint4* B = Bp + (ub + 6) * 256; s2a = __ldg(B); s2b = __ldg(B + 32); }
        consume_u<D3, KO>(zb2, af, acc, ub + 3, zp, s3a, s3b);
        if (more) { const uint4* B = Bp + (ub + 7) * 256; s3a = __ldg(B); s3b = __ldg(B + 32); }
    }
}

// per-ins template args: A=i1, B=i2, C=i3
#define CZ(IDX, A, B, Cc, BUF)                                                          \
    compute_z<DIMS_[A], DIMS_[B], DIMS_[Cc], SO_[B], OFF_[A], IDX * 125>(               \
        xs, BUF, shT, w3j_s, tid, eoff)
#define MP(IDX, A, B, Cc, BUF)                                                          \
    mma_phase<DIMS_[Cc], KO_[Cc], IDX * 8192>((const float2*)(BUF), af, acc, lane, wtile, zp)

__global__ void __launch_bounds__(NTHR, 2)
msg_kernel(const float* __restrict__ nf, const int* __restrict__ ei,
           const float* __restrict__ shg, int E, int nunits) {
    extern __shared__ float smem[];
    float* xs    = smem;                          // 288*33 = 9504
    __half* hsm  = (__half*)(xs + 288 * EPAD);    // 32*64 halves (1024 floats)
    float* zb0   = xs + 288 * EPAD + TEDGE * 32;  // 32*5*32 = 5120 (pair-packed, 8B aligned)
    float* zb1   = zb0 + 32 * 5 * 32;             // 32*5*32
    float* shT   = zb1 + 32 * 5 * 32;             // 9*33 = 297
    float* w3j_s = shT + 9 * EPAD;                // 1375
    int* srcdst  = (int*)(w3j_s + 1375);          // 64 ints
    int tid = threadIdx.x;

    // loop-invariant: w3j table (visibility covered by loop-top barrier)
    for (int idx = tid; idx < 11 * 125; idx += NTHR) w3j_s[idx] = g_w3j[idx];

    int lane = tid & 31;
    int wid = tid >> 5;
    int rtile = wid >> 2, wtile = wid & 3;
    int g = lane >> 2, tig = lane & 3;
    int er0 = rtile * 16 + g, er1 = er0 + 8;
    int wc0 = wtile * 8 + 2 * tig, wc1 = wc0 + 1;
    int zp = rtile * 8 + g;  // float2 index within (u,k) slice
    {
        // writer offset for compute_z: pairs rows (e, e+8) adjacent
    }
    int ew = tid & 31;
    int eoff = ((ew >> 4) * 16) + ((ew & 7) * 2) + ((ew >> 3) & 1);
    const uint32_t* hs2 = (const uint32_t*)hsm;

    for (int tile = blockIdx.x; tile < nunits; tile += gridDim.x) {
        int e0 = tile * TEDGE;
        __syncthreads();  // previous unit's smem readers done (and w3j_s visible, 1st iter)

        if (tid < 64) {
            int e = e0 + (tid & 31);
            int which = tid >> 5;
            srcdst[tid] = (e < E) ? ei[which * E + e] : 0;
        }
        __syncthreads();
        for (int idx = tid; idx < TEDGE * 288; idx += NTHR) {
            int e = idx / 288;
            int c = idx - e * 288;
            xs[c * EPAD + e] = (e0 + e < E) ? nf[srcdst[e] * 288 + c] : 0.f;
        }
        for (int idx = tid; idx < TEDGE * 64; idx += NTHR) {
            int e = idx >> 6;
            int c = idx & 63;
            hsm[e * 64 + c] = (e0 + e < E) ? g_Hh[(e0 + e) * 64 + c] : __float2half(0.f);
        }
        for (int idx = tid; idx < TEDGE * 9; idx += NTHR) {
            int e = idx & 31;
            int j = idx >> 5;
            shT[j * EPAD + e] = (e0 + e < E) ? shg[(e0 + e) * 9 + j] : 0.f;
        }
        __syncthreads();  // hsm/xs/shT ready

        // A fragments (h, fp16 half2-packed)
        uint32_t af[4][4];
#pragma unroll
        for (int q = 0; q < 4; q++) {
            af[q][0] = hs2[er0 * 32 + q * 8 + tig];
            af[q][1] = hs2[er1 * 32 + q * 8 + tig];
            af[q][2] = hs2[er0 * 32 + q * 8 + 4 + tig];
            af[q][3] = hs2[er1 * 32 + q * 8 + 4 + tig];
        }

        float acc[4][9];
#pragma unroll
        for (int p = 0; p < 4; p++)
#pragma unroll
            for (int k = 0; k < 9; k++) acc[p][k] = 0.f;

        // Software pipeline: z(i) in buf(i&1); iter i: write z(i+1), mma(i), barrier.
        CZ(0, 0, 0, 0, zb0);
        __syncthreads();
        CZ(1, 0, 1, 1, zb1);   MP(0, 0, 0, 0, zb0);  __syncthreads();
        CZ(2, 0, 2, 2, zb0);   MP(1, 0, 1, 1, zb1);  __syncthreads();
        CZ(3, 1, 0, 1, zb1);   MP(2, 0, 2, 2, zb0);  __syncthreads();
        CZ(4, 1, 1, 0, zb0);   MP(3, 1, 0, 1, zb1);  __syncthreads();
        CZ(5, 1, 1, 2, zb1);   MP(4, 1, 1, 0, zb0);  __syncthreads();
        CZ(6, 1, 2, 1, zb0);   MP(5, 1, 1, 2, zb1);  __syncthreads();
        CZ(7, 2, 0, 2, zb1);   MP(6, 1, 2, 1, zb0);  __syncthreads();
        CZ(8, 2, 1, 1, zb0);   MP(7, 2, 0, 2, zb1);  __syncthreads();
        CZ(9, 2, 2, 0, zb1);   MP(8, 2, 1, 1, zb0);  __syncthreads();
        CZ(10, 2, 2, 2, zb0);  MP(9, 2, 2, 0, zb1);  __syncthreads();
        MP(10, 2, 2, 2, zb0);

        // Raw accumulation into g_agg (final_kernel applies 1/sqrt(10) + self-connection).
#pragma unroll
        for (int p = 0; p < 4; p++) {
            int e = (p & 2) ? er1 : er0;
            int wcol = (p & 1) ? wc1 : wc0;
            if (e0 + e >= E) continue;
            int node = srcdst[32 + e];
            float* op = g_agg + node * 288;
            float* ac = acc[p];
            atomicAdd(op + wcol, ac[0]);
#pragma unroll
            for (int k = 0; k < 3; k++) atomicAdd(op + 32 + wcol * 3 + k, ac[1 + k]);
#pragma unroll
            for (int k = 0; k < 5; k++) atomicAdd(op + 128 + wcol * 5 + k, ac[4 + k]);
        }
    }
}

// ======================= final: out = agg/sqrt(10) + self-connection; re-zero agg ==========
__global__ void final_kernel(const float* __restrict__ nf, const float* __restrict__ w0,
                             const float* __restrict__ w1, const float* __restrict__ w2,
                             float* __restrict__ out) {
    __shared__ float xrow[288];
    int n = blockIdx.x;
    int t = threadIdx.x;
    xrow[t] = nf[n * 288 + t];
    __syncthreads();
    int O, d, wch, k;
    const float* W;
    if (t < 32)       { O = 0;   d = 1; wch = t;          k = 0;            W = w0; }
    else if (t < 128) { int r = t - 32;  O = 32;  d = 3; wch = r / 3; k = r - wch * 3; W = w1; }
    else              { int r = t - 128; O = 128; d = 5; wch = r / 5; k = r - wch * 5; W = w2; }
    float a = 0.f;
#pragma unroll
    for (int u = 0; u < 32; u++) a += xrow[O + u * d + k] * W[u * 32 + wch];
    int oidx = n * 288 + t;
    float agg = g_agg[oidx];
    g_agg[oidx] = 0.f;  // reset for next graph replay
    out[oidx] = agg * 0.31622776601683794f + a * 0.17677669529663687f;
}

// ======================= host: numpy RandomState(0) SILU_CST reproduction =======================
namespace {
struct NpRng {
    uint32_t mt[624];
    int mti;
    bool has_g;
    double g;
};
inline void rng_seed(NpRng& s, uint32_t sd) {
    s.mt[0] = sd;
    for (int i = 1; i < 624; i++)
        s.mt[i] = 1812433253u * (s.mt[i - 1] ^ (s.mt[i - 1] >> 30)) + (uint32_t)i;
    s.mti = 624;
    s.has_g = false;
    s.g = 0.0;
}
inline uint32_t rng_u32(NpRng& s) {
    if (s.mti >= 624) {
        for (int i = 0; i < 624; i++) {
            uint32_t y = (s.mt[i] & 0x80000000u) | (s.mt[(i + 1) % 624] & 0x7fffffffu);
            s.mt[i] = s.mt[(i + 397) % 624] ^ (y >> 1) ^ ((y & 1u) ? 0x9908b0dfu : 0u);
        }
        s.mti = 0;
    }
    uint32_t y = s.mt[s.mti++];
    y ^= y >> 11;
    y ^= (y << 7) & 0x9d2c5680u;
    y ^= (y << 15) & 0xefc60000u;
    y ^= y >> 18;
    return y;
}
inline double rng_double(NpRng& s) {
    uint32_t a = rng_u32(s) >> 5;
    uint32_t b = rng_u32(s) >> 6;
    return ((double)a * 67108864.0 + (double)b) / 9007199254740992.0;
}
inline double rng_gauss(NpRng& s) {
    if (s.has_g) {
        s.has_g = false;
        return s.g;
    }
    double x1, x2, r2;
    do {
        x1 = 2.0 * rng_double(s) - 1.0;
        x2 = 2.0 * rng_double(s) - 1.0;
        r2 = x1 * x1 + x2 * x2;
    } while (r2 >= 1.0 || r2 == 0.0);
    double f = sqrt(-2.0 * log(r2) / r2);
    s.g = f * x1;
    s.has_g = true;
    return f * x2;
}
inline double compute_silu_cst() {
    NpRng s;
    rng_seed(s, 0u);
    double sum = 0.0;
    for (int i = 0; i < 1000000; i++) {
        double z = rng_gauss(s);
        double sl = z / (1.0 + exp(-z));
        sum += sl * sl;
    }
    return 1.0 / sqrt(sum / 1000000.0);
}
}  // namespace

// ======================= launch =======================
extern "C" void kernel_launch(void* const* d_in, const int* in_sizes, int n_in,
                              void* d_out, int out_size) {
    const float* nf     = (const float*)d_in[0];
    const int*   ei     = (const int*)d_in[1];
    const float* sh     = (const float*)d_in[2];
    const float* radial = (const float*)d_in[3];
    const float* W1     = (const float*)d_in[4];
    const float* W2     = (const float*)d_in[5];
    const float* Wsc0   = (const float*)d_in[6];
    const float* Wsc1   = (const float*)d_in[7];
    const float* Wsc2   = (const float*)d_in[8];
    float* out = (float*)d_out;
    int N = in_sizes[0] / 288;
    int E = in_sizes[1] / 2;

    float cst = (float)compute_silu_cst();

    const size_t SMEM = (288 * EPAD + TEDGE * 32 + 2 * 32 * 5 * 32 + 9 * EPAD + 1375) * 4
                        + 64 * 4;  // ~89 KB -> 2 blocks/SM
    cudaFuncSetAttribute(msg_kernel, cudaFuncAttributeMaxDynamicSharedMemorySize, (int)SMEM);

    int ntiles = (E + TEDGE - 1) / TEDGE;        // 625
    int nb = ntiles < 592 ? ntiles : 592;        // 2 blocks/SM x 148 SMs x 2 waves

    w3j_setup_kernel<<<11, 128>>>();
    w2h_kernel<<<(64 * 11264 + 255) / 256, 256>>>(W2);
    h_kernel<<<(E + 3) / 4, 256>>>(radial, W1, cst, E);
    msg_kernel<<<nb, NTHR, SMEM>>>(nf, ei, sh, E, ntiles);
    final_kernel<<<N, 288>>>(nf, Wsc0, Wsc1, Wsc2, out);
}